// round 13
// baseline (speedup 1.0000x reference)
#include <cuda_runtime.h>
#include <cuda_bf16.h>
#include <cuda_pipeline.h>
#include <mma.h>
#include <math.h>

using namespace nvcuda;

// ---------------- problem constants ----------------
#define BATCH 32
#define NTOK  197               // 196 patches + cls
#define TOK   (BATCH*NTOK)      // 6304
#define PTOK  (BATCH*196)      // 6272
#define DIM   768
#define HEADS 12
#define DH    64
#define MLPD  3072
#define NC    1000
#define LAYERS 12
#define QKVD  (3*DIM)           // 2304

typedef __nv_bfloat16 bf16;

// ---------------- scratch (device globals; no allocation allowed) ----------------
__device__ __align__(128) float g_att  [BATCH*HEADS*NTOK*NTOK];
__device__ __align__(128) float g_x    [TOK*DIM];
__device__ __align__(128) float g_qkv  [TOK*QKVD];
__device__ __align__(128) float g_bqkv [QKVD];
__device__ __align__(128) float g_pool [BATCH*DIM];
__device__ __align__(128) float g_pooln[BATCH*DIM];
// bf16 hi/lo split buffers
__device__ __align__(128) bf16 g_hh [TOK*DIM],   g_hl [TOK*DIM];     // LN outputs
__device__ __align__(128) bf16 g_oh [TOK*DIM],   g_ol [TOK*DIM];     // attention out
__device__ __align__(128) bf16 g_mh [TOK*MLPD],  g_ml [TOK*MLPD];    // mlp1 out
__device__ __align__(128) bf16 g_ph [PTOK*DIM],  g_pl [PTOK*DIM];    // im2col patches
__device__ __align__(128) bf16 g_wth[DIM*DIM],   g_wtl[DIM*DIM];     // patch weight^T [K][N]
__device__ __align__(128) bf16 g_wqh[DIM*QKVD],  g_wql[DIM*QKVD];    // fused qkv weight [K][N]
__device__ __align__(128) bf16 g_woh[DIM*DIM],   g_wol[DIM*DIM];
__device__ __align__(128) bf16 g_w1h[DIM*MLPD],  g_w1l[DIM*MLPD];
__device__ __align__(128) bf16 g_w2h[MLPD*DIM],  g_w2l[MLPD*DIM];

// ---------------- helpers ----------------
__device__ __forceinline__ float gelu_tanh(float x) {
    float x3 = x * x * x;
    float t  = tanhf(0.7978845608028654f * (x + 0.044715f * x3));
    return 0.5f * x * (1.0f + t);
}
__device__ __forceinline__ void split2(float v, bf16& h, bf16& l) {
    h = __float2bfloat16(v);
    l = __float2bfloat16(v - __bfloat162float(h));
}

// =====================================================================
// bf16-split GEMM, 4-stage cp.async ring in dynamic smem.
// C = act(Ah@Bh + Al@Bh + Ah@Bl + bias). N%128==0, K%16==0, M guarded.
// A (hi/lo): [M][K] bf16 row-major. B (hi/lo): [K][N] bf16 row-major.
// 128x128 tile, BK=16, 256 thr = 8 warps (2m x 4n), warp tile 64x32.
// mode 0: C(f32) = sum + bias (+res).  mode 1: gelu -> split to Ch/Cl.
// =====================================================================
#define STG_A   (128*24)                 // elements per A operand per stage (pad 24)
#define STG_B   (16*136)                 // elements per B operand per stage (pad 136)
#define NSTG    4
#define OFF_AH  0
#define OFF_AL  (NSTG*STG_A*2)
#define OFF_BH  (2*NSTG*STG_A*2)
#define OFF_BL  (2*NSTG*STG_A*2 + NSTG*STG_B*2)
#define GEMM_DSMEM (2*NSTG*STG_A*2 + 2*NSTG*STG_B*2)   // 83968 B

__global__ __launch_bounds__(256, 2)
void gemm_bf16s(const bf16* __restrict__ Ah, const bf16* __restrict__ Al,
                const bf16* __restrict__ Bh, const bf16* __restrict__ Bl,
                const float* __restrict__ bias, const float* __restrict__ res,
                float* __restrict__ C, bf16* __restrict__ Ch, bf16* __restrict__ Cl,
                int M, int N, int K, int mode)
{
    extern __shared__ __align__(16) char dsm[];
    bf16* AhS = (bf16*)(dsm + OFF_AH);
    bf16* AlS = (bf16*)(dsm + OFF_AL);
    bf16* BhS = (bf16*)(dsm + OFF_BH);
    bf16* BlS = (bf16*)(dsm + OFF_BL);

    const int tid  = threadIdx.x;
    const int m0   = blockIdx.y * 128;
    const int n0   = blockIdx.x * 128;
    const int warp = tid >> 5;
    const int wm   = warp & 1;           // 0..1 -> 64-row half
    const int wn   = warp >> 1;          // 0..3 -> 32-col group

    // cp.async assignments (16B chunks)
    const int arow = tid >> 1,  achk = (tid & 1) * 8;    // A: 128 rows x 2 chunks
    const int brow = tid >> 4,  bchk = (tid & 15) * 8;   // B: 16 rows x 16 chunks
    const bool ap  = (m0 + arow) < M;
    const long abase = ap ? ((long)(m0 + arow) * K + achk) : 0;
    const size_t az  = ap ? 0 : 16;      // zero-fill when row OOB

    wmma::fragment<wmma::accumulator, 16, 16, 16, float> acc[4][2];
    #pragma unroll
    for (int i = 0; i < 4; i++)
        #pragma unroll
        for (int j = 0; j < 2; j++)
            wmma::fill_fragment(acc[i][j], 0.0f);

    const int KT = K >> 4;

    // issue stage for k-chunk kt into ring slot s
    auto issue = [&](int kt, int s) {
        const int k0 = kt << 4;
        __pipeline_memcpy_async(AhS + s * STG_A + arow * 24 + achk,
                                Ah + abase + (ap ? k0 : 0), 16, az);
        __pipeline_memcpy_async(AlS + s * STG_A + arow * 24 + achk,
                                Al + abase + (ap ? k0 : 0), 16, az);
        const long boff = (long)(k0 + brow) * N + n0 + bchk;
        __pipeline_memcpy_async(BhS + s * STG_B + brow * 136 + bchk, Bh + boff, 16, 0);
        __pipeline_memcpy_async(BlS + s * STG_B + brow * 136 + bchk, Bl + boff, 16, 0);
    };

    // prologue: 3 stages in flight
    #pragma unroll
    for (int s = 0; s < 3; s++) {
        if (s < KT) issue(s, s);
        __pipeline_commit();
    }

    for (int kt = 0; kt < KT; kt++) {
        __pipeline_wait_prior(2);        // stage kt ready
        __syncthreads();                 // everyone done with slot (kt-1)&3, data visible
        if (kt + 3 < KT) issue(kt + 3, (kt + 3) & 3);
        __pipeline_commit();

        const int cur = kt & 3;
        wmma::fragment<wmma::matrix_b, 16, 16, 16, bf16, wmma::row_major> fbh[2], fbl[2];
        #pragma unroll
        for (int j = 0; j < 2; j++) {
            wmma::load_matrix_sync(fbh[j], BhS + cur * STG_B + wn * 32 + j * 16, 136);
            wmma::load_matrix_sync(fbl[j], BlS + cur * STG_B + wn * 32 + j * 16, 136);
        }
        #pragma unroll
        for (int i = 0; i < 4; i++) {
            wmma::fragment<wmma::matrix_a, 16, 16, 16, bf16, wmma::row_major> fah, fal;
            wmma::load_matrix_sync(fah, AhS + cur * STG_A + (wm * 64 + i * 16) * 24, 24);
            wmma::load_matrix_sync(fal, AlS + cur * STG_A + (wm * 64 + i * 16) * 24, 24);
            #pragma unroll
            for (int j = 0; j < 2; j++) {
                wmma::mma_sync(acc[i][j], fah, fbh[j], acc[i][j]);
                wmma::mma_sync(acc[i][j], fal, fbh[j], acc[i][j]);
                wmma::mma_sync(acc[i][j], fah, fbl[j], acc[i][j]);
            }
        }
    }
    __syncthreads();   // before reusing dsm as epilogue bounce

    // epilogue: two 64-row phases through smem (64 x 132 f32)
    float* Cep = (float*)dsm;
    #pragma unroll
    for (int pm = 0; pm < 2; pm++) {
        if (wm == pm) {
            #pragma unroll
            for (int i = 0; i < 4; i++)
                #pragma unroll
                for (int j = 0; j < 2; j++)
                    wmma::store_matrix_sync(Cep + (i * 16) * 132 + wn * 32 + j * 16,
                                            acc[i][j], 132, wmma::mem_row_major);
        }
        __syncthreads();
        #pragma unroll
        for (int l = 0; l < 32; l++) {
            int e   = tid + 256 * l;
            int row = e >> 7;
            int col = e & 127;
            int gm  = m0 + pm * 64 + row;
            if (gm < M) {
                int gn = n0 + col;
                float vv = Cep[row * 132 + col] + bias[gn];
                if (mode == 1) {
                    vv = gelu_tanh(vv);
                    bf16 h, lo; split2(vv, h, lo);
                    Ch[(long)gm * N + gn] = h;
                    Cl[(long)gm * N + gn] = lo;
                } else {
                    if (res) vv += res[(long)gm * N + gn];
                    C[(long)gm * N + gn] = vv;
                }
            }
        }
        __syncthreads();
    }
}

// ---------------- fp32 SGEMM (head only: M=32, N=1000) ----------------
__global__ __launch_bounds__(256, 2)
void sgemm128(const float* __restrict__ A, const float* __restrict__ B,
              const float* __restrict__ bias, float* __restrict__ C,
              int M, int N, int K)
{
    __shared__ float As[16][128];
    __shared__ float Bs[16][128];

    const int tid = threadIdx.x;
    const int tx  = tid & 15;
    const int ty  = tid >> 4;
    const int m0  = blockIdx.y * 128;
    const int n0  = blockIdx.x * 128;

    float acc[8][8];
    #pragma unroll
    for (int i = 0; i < 8; i++)
        #pragma unroll
        for (int j = 0; j < 8; j++) acc[i][j] = 0.f;

    for (int k0 = 0; k0 < K; k0 += 16) {
        #pragma unroll
        for (int l = 0; l < 2; l++) {
            int e   = tid + 256 * l;
            int row = e >> 2;
            int c4  = (e & 3) * 4;
            int gm  = m0 + row;
            float4 av = make_float4(0.f, 0.f, 0.f, 0.f);
            if (gm < M) av = *(const float4*)(A + (long)gm * K + k0 + c4);
            As[c4 + 0][row] = av.x;
            As[c4 + 1][row] = av.y;
            As[c4 + 2][row] = av.z;
            As[c4 + 3][row] = av.w;
        }
        #pragma unroll
        for (int l = 0; l < 2; l++) {
            int e  = tid + 256 * l;
            int r  = e >> 5;
            int c  = (e & 31) * 4;
            int gn = n0 + c;
            const float* src = B + (long)(k0 + r) * N + gn;
            float4 bv;
            if (gn + 3 < N) {
                bv = *(const float4*)src;
            } else {
                bv.x = (gn + 0 < N) ? src[0] : 0.f;
                bv.y = (gn + 1 < N) ? src[1] : 0.f;
                bv.z = (gn + 2 < N) ? src[2] : 0.f;
                bv.w = (gn + 3 < N) ? src[3] : 0.f;
            }
            *(float4*)&Bs[r][c] = bv;
        }
        __syncthreads();

        #pragma unroll
        for (int kk = 0; kk < 16; kk++) {
            float ar[8], br[8];
            *(float4*)&ar[0] = *(const float4*)&As[kk][ty * 4];
            *(float4*)&ar[4] = *(const float4*)&As[kk][64 + ty * 4];
            *(float4*)&br[0] = *(const float4*)&Bs[kk][tx * 4];
            *(float4*)&br[4] = *(const float4*)&Bs[kk][64 + tx * 4];
            #pragma unroll
            for (int i = 0; i < 8; i++)
                #pragma unroll
                for (int j = 0; j < 8; j++)
                    acc[i][j] += ar[i] * br[j];
        }
        __syncthreads();
    }

    #pragma unroll
    for (int i = 0; i < 8; i++) {
        int gm = m0 + ((i < 4) ? (ty * 4 + i) : (64 + ty * 4 + i - 4));
        if (gm >= M) continue;
        #pragma unroll
        for (int j = 0; j < 8; j++) {
            int gn = n0 + ((j < 4) ? (tx * 4 + j) : (64 + tx * 4 + j - 4));
            if (gn >= N) continue;
            C[(long)gm * N + gn] = acc[i][j] + bias[gn];
        }
    }
}

// ---------------- LayerNorm -> bf16 hi/lo split output ----------------
__global__ void ln_split_kernel(const float* __restrict__ x, const float* __restrict__ g,
                                const float* __restrict__ b,
                                bf16* __restrict__ oh, bf16* __restrict__ ol)
{
    const int row = blockIdx.x;
    const int t   = threadIdx.x;   // 256
    const float* xr = x + (long)row * DIM;

    float v[3];
    float s = 0.f, s2 = 0.f;
    #pragma unroll
    for (int i = 0; i < 3; i++) {
        v[i] = xr[t + 256 * i];
        s  += v[i];
        s2 += v[i] * v[i];
    }
    #pragma unroll
    for (int off = 16; off; off >>= 1) {
        s  += __shfl_down_sync(0xffffffffu, s,  off);
        s2 += __shfl_down_sync(0xffffffffu, s2, off);
    }
    __shared__ float rs[8], rs2[8];
    int wid = t >> 5, lane = t & 31;
    if (lane == 0) { rs[wid] = s; rs2[wid] = s2; }
    __syncthreads();
    if (t == 0) {
        float a = 0.f, c = 0.f;
        #pragma unroll
        for (int i = 0; i < 8; i++) { a += rs[i]; c += rs2[i]; }
        rs[0] = a; rs2[0] = c;
    }
    __syncthreads();
    float mean = rs[0] * (1.f / DIM);
    float var  = rs2[0] * (1.f / DIM) - mean * mean;
    float rstd = rsqrtf(var + 1e-5f);
    #pragma unroll
    for (int i = 0; i < 3; i++) {
        int idx = t + 256 * i;
        float vv = (v[i] - mean) * rstd * g[idx] + b[idx];
        bf16 h, lo; split2(vv, h, lo);
        oh[(long)row * DIM + idx] = h;
        ol[(long)row * DIM + idx] = lo;
    }
}

// ---------------- LayerNorm fp32 out (head) ----------------
__global__ void ln_kernel(const float* __restrict__ x, const float* __restrict__ g,
                          const float* __restrict__ b, float* __restrict__ out)
{
    const int row = blockIdx.x;
    const int t   = threadIdx.x;
    const float* xr = x + (long)row * DIM;

    float v[3];
    float s = 0.f, s2 = 0.f;
    #pragma unroll
    for (int i = 0; i < 3; i++) {
        v[i] = xr[t + 256 * i];
        s  += v[i];
        s2 += v[i] * v[i];
    }
    #pragma unroll
    for (int off = 16; off; off >>= 1) {
        s  += __shfl_down_sync(0xffffffffu, s,  off);
        s2 += __shfl_down_sync(0xffffffffu, s2, off);
    }
    __shared__ float rs[8], rs2[8];
    int wid = t >> 5, lane = t & 31;
    if (lane == 0) { rs[wid] = s; rs2[wid] = s2; }
    __syncthreads();
    if (t == 0) {
        float a = 0.f, c = 0.f;
        #pragma unroll
        for (int i = 0; i < 8; i++) { a += rs[i]; c += rs2[i]; }
        rs[0] = a; rs2[0] = c;
    }
    __syncthreads();
    float mean = rs[0] * (1.f / DIM);
    float var  = rs2[0] * (1.f / DIM) - mean * mean;
    float rstd = rsqrtf(var + 1e-5f);
    float* orow = out + (long)row * DIM;
    #pragma unroll
    for (int i = 0; i < 3; i++) {
        int idx = t + 256 * i;
        orow[idx] = (v[i] - mean) * rstd * g[idx] + b[idx];
    }
}

// ---------------- generic fp32 -> bf16 hi/lo split ----------------
__global__ void split_kernel(const float* __restrict__ s, bf16* __restrict__ h,
                             bf16* __restrict__ l, int n)
{
    for (int i = blockIdx.x * blockDim.x + threadIdx.x; i < n; i += gridDim.x * blockDim.x) {
        bf16 hh, ll; split2(s[i], hh, ll);
        h[i] = hh; l[i] = ll;
    }
}

// ---------------- patch embedding support ----------------
__global__ void im2col_split_kernel(const float* __restrict__ imgs,
                                    bf16* __restrict__ ph, bf16* __restrict__ pl)
{
    long total = (long)PTOK * DIM;
    for (long idx = (long)blockIdx.x * blockDim.x + threadIdx.x; idx < total;
         idx += (long)gridDim.x * blockDim.x) {
        int row = (int)(idx / DIM);
        int col = (int)(idx % DIM);
        int b = row / 196, p = row % 196;
        int phh = p / 14, pw = p % 14;
        int c = col >> 8, rem = col & 255;
        int i = rem >> 4, j = rem & 15;
        float v = imgs[(((long)(b * 3 + c) * 224) + phh * 16 + i) * 224 + pw * 16 + j];
        bf16 h, lo; split2(v, h, lo);
        ph[idx] = h; pl[idx] = lo;
    }
}

// transpose 768x768 (OI -> IO) + split (patch weight [N][K] -> [K][N] bf16)
__global__ void transpose768_split_kernel(const float* __restrict__ w,
                                          bf16* __restrict__ wh, bf16* __restrict__ wl)
{
    int idx = blockIdx.x * 256 + threadIdx.x;
    if (idx < DIM * DIM) {
        int d = idx / DIM, k = idx % DIM;
        bf16 h, lo; split2(w[idx], h, lo);
        wh[k * DIM + d] = h; wl[k * DIM + d] = lo;
    }
}

// pack per-layer qkv weights (split, [K][N] layout) — weights already [K][N]
__global__ void qkv_pack_split_kernel(const float* __restrict__ wq, const float* __restrict__ wk,
                                      const float* __restrict__ wv,
                                      bf16* __restrict__ wh, bf16* __restrict__ wl)
{
    int total = DIM * QKVD;
    for (int idx = blockIdx.x * blockDim.x + threadIdx.x; idx < total;
         idx += gridDim.x * blockDim.x) {
        int k = idx / QKVD, n = idx % QKVD;
        int sel = n / DIM, c = n % DIM;
        const float* src = (sel == 0) ? wq : (sel == 1) ? wk : wv;
        bf16 h, lo; split2(src[k * DIM + c], h, lo);
        wh[idx] = h; wl[idx] = lo;
    }
}

// qkv bias concat
__global__ void bias3_kernel(const float* __restrict__ bq, const float* __restrict__ bk,
                             const float* __restrict__ bv, float* __restrict__ b)
{
    int i = blockIdx.x * 256 + threadIdx.x;
    if (i < QKVD) {
        int sel = i / DIM, c = i % DIM;
        b[i] = (sel == 0 ? bq : (sel == 1 ? bk : bv))[c];
    }
}

// assemble tokens
__global__ void assemble_kernel(const float* __restrict__ pe, const float* __restrict__ cls,
                                const float* __restrict__ pos, float* __restrict__ x)
{
    long total = (long)TOK * DIM;
    for (long idx = (long)blockIdx.x * blockDim.x + threadIdx.x; idx < total;
         idx += (long)gridDim.x * blockDim.x) {
        int row = (int)(idx / DIM);
        int d   = (int)(idx % DIM);
        int b = row / NTOK, n = row % NTOK;
        float v = (n == 0) ? cls[d] : pe[((long)(b * 196 + n - 1)) * DIM + d];
        x[idx] = v + pos[n * DIM + d];
    }
}

// ---------------- attention (q/k/v inside fused qkv buffer, row stride QKVD) ----
__global__ void attn_scores_kernel(const float* __restrict__ qkv, float* __restrict__ s)
{
    __shared__ float Qs[16][65], Ks[16][65];
    int bh = blockIdx.z;
    int b = bh / HEADS, hh = bh % HEADS;
    int tx = threadIdx.x, ty = threadIdx.y;
    int tid = ty * 16 + tx;
    int nbase = blockIdx.y * 16, mbase = blockIdx.x * 16;

    #pragma unroll
    for (int l = 0; l < 4; l++) {
        int e = tid + l * 256;
        int r = e >> 6, d = e & 63;
        int nq = nbase + r;
        Qs[r][d] = (nq < NTOK) ? qkv[((long)(b * NTOK + nq)) * QKVD + hh * DH + d] : 0.f;
        int mk = mbase + r;
        Ks[r][d] = (mk < NTOK) ? qkv[((long)(b * NTOK + mk)) * QKVD + DIM + hh * DH + d] : 0.f;
    }
    __syncthreads();

    float acc = 0.f;
    #pragma unroll
    for (int d = 0; d < DH; d++) acc += Qs[ty][d] * Ks[tx][d];

    int n = nbase + ty, m = mbase + tx;
    if (n < NTOK && m < NTOK)
        s[((long)bh * NTOK + n) * NTOK + m] = acc * 0.125f;
}

__global__ void softmax_kernel(float* __restrict__ s, int rows)
{
    int warp = (blockIdx.x * blockDim.x + threadIdx.x) >> 5;
    int lane = threadIdx.x & 31;
    if (warp >= rows) return;
    float* r = s + (long)warp * NTOK;

    float vals[7];
    float mx = -1e30f;
    #pragma unroll
    for (int w = 0; w < 7; w++) {
        int j = lane + 32 * w;
        vals[w] = (j < NTOK) ? r[j] : -1e30f;
        mx = fmaxf(mx, vals[w]);
    }
    #pragma unroll
    for (int off = 16; off; off >>= 1)
        mx = fmaxf(mx, __shfl_xor_sync(0xffffffffu, mx, off));

    float sum = 0.f;
    #pragma unroll
    for (int w = 0; w < 7; w++) {
        int j = lane + 32 * w;
        if (j < NTOK) { vals[w] = expf(vals[w] - mx); sum += vals[w]; }
    }
    #pragma unroll
    for (int off = 16; off; off >>= 1)
        sum += __shfl_xor_sync(0xffffffffu, sum, off);

    float inv = 1.f / sum;
    #pragma unroll
    for (int w = 0; w < 7; w++) {
        int j = lane + 32 * w;
        if (j < NTOK) r[j] = vals[w] * inv;
    }
}

// o = P @ V, written as bf16 hi/lo split
__global__ void attn_av_kernel(const float* __restrict__ s, const float* __restrict__ qkv,
                               bf16* __restrict__ oh, bf16* __restrict__ ol)
{
    __shared__ float Ps[16][17], Vs[16][17];
    int bh = blockIdx.z;
    int b = bh / HEADS, hh = bh % HEADS;
    int tx = threadIdx.x, ty = threadIdx.y;
    int n = blockIdx.y * 16 + ty;
    int d = blockIdx.x * 16 + tx;

    float acc = 0.f;
    for (int mt = 0; mt < 13; mt++) {
        int mP = mt * 16 + tx;
        Ps[ty][tx] = (n < NTOK && mP < NTOK) ? s[((long)bh * NTOK + n) * NTOK + mP] : 0.f;
        int mV = mt * 16 + ty;
        Vs[ty][tx] = (mV < NTOK)
            ? qkv[((long)(b * NTOK + mV)) * QKVD + 2 * DIM + hh * DH + d] : 0.f;
        __syncthreads();
        #pragma unroll
        for (int kk = 0; kk < 16; kk++) acc += Ps[ty][kk] * Vs[kk][tx];
        __syncthreads();
    }
    if (n < NTOK) {
        bf16 h, lo; split2(acc, h, lo);
        long idx = ((long)(b * NTOK + n)) * DIM + hh * DH + d;
        oh[idx] = h; ol[idx] = lo;
    }
}

// ---------------- mean pool ----------------
__global__ void pool_kernel(const float* __restrict__ x, float* __restrict__ out)
{
    int b = blockIdx.x;
    for (int d = threadIdx.x; d < DIM; d += blockDim.x) {
        float s = 0.f;
        for (int n = 0; n < NTOK; n++)
            s += x[((long)(b * NTOK + n)) * DIM + d];
        out[b * DIM + d] = s * (1.f / NTOK);
    }
}

// ---------------- host ----------------
extern "C" void kernel_launch(void* const* d_in, const int* in_sizes, int n_in,
                              void* d_out, int out_size)
{
    const float* imgs    = (const float*)d_in[0];
    const float* patch_w = (const float*)d_in[1];
    const float* patch_b = (const float*)d_in[2];
    const float* cls     = (const float*)d_in[3];
    const float* pos     = (const float*)d_in[4];
    const float* ln1_g   = (const float*)d_in[5];
    const float* ln1_b   = (const float*)d_in[6];
    const float* wq      = (const float*)d_in[7];
    const float* bq      = (const float*)d_in[8];
    const float* wk      = (const float*)d_in[9];
    const float* bk      = (const float*)d_in[10];
    const float* wv      = (const float*)d_in[11];
    const float* bv      = (const float*)d_in[12];
    const float* wo      = (const float*)d_in[13];
    const float* bo      = (const float*)d_in[14];
    const float* ln2_g   = (const float*)d_in[15];
    const float* ln2_b   = (const float*)d_in[16];
    const float* w1      = (const float*)d_in[17];
    const float* b1      = (const float*)d_in[18];
    const float* w2      = (const float*)d_in[19];
    const float* b2      = (const float*)d_in[20];
    const float* hn_g    = (const float*)d_in[21];
    const float* hn_b    = (const float*)d_in[22];
    const float* hw      = (const float*)d_in[23];
    const float* hb      = (const float*)d_in[24];
    float* out = (float*)d_out;

    float *att, *x, *qkv, *bqkv, *pool, *pooln;
    bf16 *hh, *hl, *oh, *ol, *mh, *ml, *ph, *pl, *wth, *wtl, *wqh, *wql;
    bf16 *woh, *wol, *w1h, *w1l, *w2h, *w2l;
    cudaGetSymbolAddress((void**)&att,   g_att);
    cudaGetSymbolAddress((void**)&x,     g_x);
    cudaGetSymbolAddress((void**)&qkv,   g_qkv);
    cudaGetSymbolAddress((void**)&bqkv,  g_bqkv);
    cudaGetSymbolAddress((void**)&pool,  g_pool);
    cudaGetSymbolAddress((void**)&pooln, g_pooln);
    cudaGetSymbolAddress((void**)&hh,  g_hh);  cudaGetSymbolAddress((void**)&hl,  g_hl);
    cudaGetSymbolAddress((void**)&oh,  g_oh);  cudaGetSymbolAddress((void**)&ol,  g_ol);
    cudaGetSymbolAddress((void**)&mh,  g_mh);  cudaGetSymbolAddress((void**)&ml,  g_ml);
    cudaGetSymbolAddress((void**)&ph,  g_ph);  cudaGetSymbolAddress((void**)&pl,  g_pl);
    cudaGetSymbolAddress((void**)&wth, g_wth); cudaGetSymbolAddress((void**)&wtl, g_wtl);
    cudaGetSymbolAddress((void**)&wqh, g_wqh); cudaGetSymbolAddress((void**)&wql, g_wql);
    cudaGetSymbolAddress((void**)&woh, g_woh); cudaGetSymbolAddress((void**)&wol, g_wol);
    cudaGetSymbolAddress((void**)&w1h, g_w1h); cudaGetSymbolAddress((void**)&w1l, g_w1l);
    cudaGetSymbolAddress((void**)&w2h, g_w2h); cudaGetSymbolAddress((void**)&w2l, g_w2l);

    cudaFuncSetAttribute(gemm_bf16s, cudaFuncAttributeMaxDynamicSharedMemorySize, GEMM_DSMEM);

    auto gemmS = [](const bf16* Ah, const bf16* Al, const bf16* Bh, const bf16* Bl,
                    const float* bias, const float* res, float* C, bf16* Ch, bf16* Cl,
                    int M, int N, int K, int mode) {
        dim3 grid(N / 128, (M + 127) / 128);
        gemm_bf16s<<<grid, 256, GEMM_DSMEM>>>(Ah, Al, Bh, Bl, bias, res, C, Ch, Cl, M, N, K, mode);
    };

    // ---- patch embedding (bias3 for layer 0 inserted as 3rd launch so the
    //      profiler's fixed capture slot (4th launch) lands on gemm_bf16s) ----
    im2col_split_kernel<<<4096, 256>>>(imgs, ph, pl);                              // 1
    transpose768_split_kernel<<<(DIM * DIM + 255) / 256, 256>>>(patch_w, wth, wtl); // 2
    bias3_kernel<<<9, 256>>>(bq, bk, bv, bqkv);                                    // 3 (layer 0)
    gemmS(ph, pl, wth, wtl, patch_b, nullptr, qkv, nullptr, nullptr, PTOK, DIM, DIM, 0); // 4
    assemble_kernel<<<4096, 256>>>(qkv, cls, pos, x);

    // ---- transformer layers ----
    const int rows_sm = BATCH * HEADS * NTOK;
    for (int i = 0; i < LAYERS; i++) {
        qkv_pack_split_kernel<<<2048, 256>>>(wq + (long)i * DIM * DIM, wk + (long)i * DIM * DIM,
                                             wv + (long)i * DIM * DIM, wqh, wql);
        if (i > 0) bias3_kernel<<<9, 256>>>(bq + i * DIM, bk + i * DIM, bv + i * DIM, bqkv);
        split_kernel<<<1024, 256>>>(wo + (long)i * DIM * DIM, woh, wol, DIM * DIM);
        split_kernel<<<2048, 256>>>(w1 + (long)i * DIM * MLPD, w1h, w1l, DIM * MLPD);
        split_kernel<<<2048, 256>>>(w2 + (long)i * MLPD * DIM, w2h, w2l, MLPD * DIM);

        ln_split_kernel<<<TOK, 256>>>(x, ln1_g + i * DIM, ln1_b + i * DIM, hh, hl);
        gemmS(hh, hl, wqh, wql, bqkv, nullptr, qkv, nullptr, nullptr, TOK, QKVD, DIM, 0);

        attn_scores_kernel<<<dim3(13, 13, BATCH * HEADS), dim3(16, 16)>>>(qkv, att);
        softmax_kernel<<<(rows_sm * 32 + 255) / 256, 256>>>(att, rows_sm);
        attn_av_kernel<<<dim3(4, 13, BATCH * HEADS), dim3(16, 16)>>>(att, qkv, oh, ol);

        gemmS(oh, ol, woh, wol, bo + i * DIM, x, x, nullptr, nullptr, TOK, DIM, DIM, 0);

        ln_split_kernel<<<TOK, 256>>>(x, ln2_g + i * DIM, ln2_b + i * DIM, hh, hl);
        gemmS(hh, hl, w1h, w1l, b1 + i * MLPD, nullptr, nullptr, mh, ml, TOK, MLPD, DIM, 1);
        gemmS(mh, ml, w2h, w2l, b2 + i * DIM, x, x, nullptr, nullptr, TOK, DIM, MLPD, 0);
    }

    // ---- head ----
    pool_kernel<<<BATCH, 256>>>(x, pool);
    ln_kernel<<<BATCH, 256>>>(pool, hn_g, hn_b, pooln);
    {
        dim3 grid((NC + 127) / 128, 1);
        sgemm128<<<grid, 256>>>(pooln, hw, hb, out, BATCH, NC, DIM);
    }
}

// round 14
// speedup vs baseline: 1.0004x; 1.0004x over previous
#include <cuda_runtime.h>
#include <cuda_bf16.h>
#include <cuda_pipeline.h>
#include <mma.h>
#include <math.h>

using namespace nvcuda;

// ---------------- problem constants ----------------
#define BATCH 32
#define NTOK  197               // 196 patches + cls
#define TOK   (BATCH*NTOK)      // 6304
#define PTOK  (BATCH*196)       // 6272
#define DIM   768
#define HEADS 12
#define DH    64
#define MLPD  3072
#define NC    1000
#define LAYERS 12
#define QKVD  (3*DIM)           // 2304

typedef __nv_bfloat16 bf16;

// ---------------- scratch (device globals; no allocation allowed) ----------------
__device__ __align__(128) float g_att  [BATCH*HEADS*NTOK*NTOK];
__device__ __align__(128) float g_x    [TOK*DIM];
__device__ __align__(128) float g_qkv  [TOK*QKVD];
__device__ __align__(128) float g_bqkv [QKVD];
__device__ __align__(128) float g_pool [BATCH*DIM];
__device__ __align__(128) float g_pooln[BATCH*DIM];
// bf16 hi/lo split buffers
__device__ __align__(128) bf16 g_hh [TOK*DIM],   g_hl [TOK*DIM];     // LN outputs
__device__ __align__(128) bf16 g_oh [TOK*DIM],   g_ol [TOK*DIM];     // attention out
__device__ __align__(128) bf16 g_mh [TOK*MLPD],  g_ml [TOK*MLPD];    // mlp1 out
__device__ __align__(128) bf16 g_ph [PTOK*DIM],  g_pl [PTOK*DIM];    // im2col patches
__device__ __align__(128) bf16 g_wth[DIM*DIM],   g_wtl[DIM*DIM];     // patch weight^T [K][N]
__device__ __align__(128) bf16 g_wqh[DIM*QKVD],  g_wql[DIM*QKVD];    // fused qkv weight [K][N]
__device__ __align__(128) bf16 g_woh[DIM*DIM],   g_wol[DIM*DIM];
__device__ __align__(128) bf16 g_w1h[DIM*MLPD],  g_w1l[DIM*MLPD];
__device__ __align__(128) bf16 g_w2h[MLPD*DIM],  g_w2l[MLPD*DIM];

// ---------------- helpers ----------------
__device__ __forceinline__ float gelu_tanh(float x) {
    float x3 = x * x * x;
    float t  = tanhf(0.7978845608028654f * (x + 0.044715f * x3));
    return 0.5f * x * (1.0f + t);
}
__device__ __forceinline__ void split2(float v, bf16& h, bf16& l) {
    h = __float2bfloat16(v);
    l = __float2bfloat16(v - __bfloat162float(h));
}

// =====================================================================
// bf16-split GEMM, 4-stage cp.async ring, TERM-MAJOR MMA issue order
// (RAW distance 4 between HMMAs on the same accumulator).
// C = act(Ah@Bh + Al@Bh + Ah@Bl + bias). N%128==0, K%16==0, M guarded.
// A (hi/lo): [M][K] bf16 row-major. B (hi/lo): [K][N] bf16 row-major.
// 128x128 tile, BK=16, 256 thr = 8 warps (2m x 4n), warp tile 64x32.
// mode 0: C(f32) = sum + bias (+res).  mode 1: gelu -> split to Ch/Cl.
// =====================================================================
#define STG_A   (128*24)                 // elements per A operand per stage (pad 24)
#define STG_B   (16*136)                 // elements per B operand per stage (pad 136)
#define NSTG    4
#define OFF_AH  0
#define OFF_AL  (NSTG*STG_A*2)
#define OFF_BH  (2*NSTG*STG_A*2)
#define OFF_BL  (2*NSTG*STG_A*2 + NSTG*STG_B*2)
#define GEMM_DSMEM (2*NSTG*STG_A*2 + 2*NSTG*STG_B*2)   // 83968 B

__global__ __launch_bounds__(256, 2)
void gemm_bf16s(const bf16* __restrict__ Ah, const bf16* __restrict__ Al,
                const bf16* __restrict__ Bh, const bf16* __restrict__ Bl,
                const float* __restrict__ bias, const float* __restrict__ res,
                float* __restrict__ C, bf16* __restrict__ Ch, bf16* __restrict__ Cl,
                int M, int N, int K, int mode)
{
    extern __shared__ __align__(16) char dsm[];
    bf16* AhS = (bf16*)(dsm + OFF_AH);
    bf16* AlS = (bf16*)(dsm + OFF_AL);
    bf16* BhS = (bf16*)(dsm + OFF_BH);
    bf16* BlS = (bf16*)(dsm + OFF_BL);

    const int tid  = threadIdx.x;
    const int m0   = blockIdx.y * 128;
    const int n0   = blockIdx.x * 128;
    const int warp = tid >> 5;
    const int wm   = warp & 1;           // 0..1 -> 64-row half
    const int wn   = warp >> 1;          // 0..3 -> 32-col group

    // cp.async assignments (16B chunks)
    const int arow = tid >> 1,  achk = (tid & 1) * 8;    // A: 128 rows x 2 chunks
    const int brow = tid >> 4,  bchk = (tid & 15) * 8;   // B: 16 rows x 16 chunks
    const bool ap  = (m0 + arow) < M;
    const long abase = ap ? ((long)(m0 + arow) * K + achk) : 0;
    const size_t az  = ap ? 0 : 16;      // zero-fill when row OOB

    wmma::fragment<wmma::accumulator, 16, 16, 16, float> acc[4][2];
    #pragma unroll
    for (int i = 0; i < 4; i++)
        #pragma unroll
        for (int j = 0; j < 2; j++)
            wmma::fill_fragment(acc[i][j], 0.0f);

    const int KT = K >> 4;

    // issue stage for k-chunk kt into ring slot s
    auto issue = [&](int kt, int s) {
        const int k0 = kt << 4;
        __pipeline_memcpy_async(AhS + s * STG_A + arow * 24 + achk,
                                Ah + abase + (ap ? k0 : 0), 16, az);
        __pipeline_memcpy_async(AlS + s * STG_A + arow * 24 + achk,
                                Al + abase + (ap ? k0 : 0), 16, az);
        const long boff = (long)(k0 + brow) * N + n0 + bchk;
        __pipeline_memcpy_async(BhS + s * STG_B + brow * 136 + bchk, Bh + boff, 16, 0);
        __pipeline_memcpy_async(BlS + s * STG_B + brow * 136 + bchk, Bl + boff, 16, 0);
    };

    // prologue: 3 stages in flight
    #pragma unroll
    for (int s = 0; s < 3; s++) {
        if (s < KT) issue(s, s);
        __pipeline_commit();
    }

    for (int kt = 0; kt < KT; kt++) {
        __pipeline_wait_prior(2);        // stage kt ready
        __syncthreads();                 // everyone done with slot (kt-1)&3, data visible
        if (kt + 3 < KT) issue(kt + 3, (kt + 3) & 3);
        __pipeline_commit();

        const int cur = kt & 3;
        wmma::fragment<wmma::matrix_b, 16, 16, 16, bf16, wmma::row_major> fbh[2], fbl[2];
        #pragma unroll
        for (int j = 0; j < 2; j++) {
            wmma::load_matrix_sync(fbh[j], BhS + cur * STG_B + wn * 32 + j * 16, 136);
            wmma::load_matrix_sync(fbl[j], BlS + cur * STG_B + wn * 32 + j * 16, 136);
        }
        // process m-tiles in pairs; issue MMAs term-major so consecutive
        // HMMAs hit different accumulators (RAW distance 4)
        #pragma unroll
        for (int ip = 0; ip < 4; ip += 2) {
            wmma::fragment<wmma::matrix_a, 16, 16, 16, bf16, wmma::row_major> fah0, fal0, fah1, fal1;
            wmma::load_matrix_sync(fah0, AhS + cur * STG_A + (wm * 64 + ip * 16) * 24, 24);
            wmma::load_matrix_sync(fah1, AhS + cur * STG_A + (wm * 64 + (ip + 1) * 16) * 24, 24);
            wmma::load_matrix_sync(fal0, AlS + cur * STG_A + (wm * 64 + ip * 16) * 24, 24);
            wmma::load_matrix_sync(fal1, AlS + cur * STG_A + (wm * 64 + (ip + 1) * 16) * 24, 24);
            // term hi*hi
            wmma::mma_sync(acc[ip][0],     fah0, fbh[0], acc[ip][0]);
            wmma::mma_sync(acc[ip + 1][0], fah1, fbh[0], acc[ip + 1][0]);
            wmma::mma_sync(acc[ip][1],     fah0, fbh[1], acc[ip][1]);
            wmma::mma_sync(acc[ip + 1][1], fah1, fbh[1], acc[ip + 1][1]);
            // term lo*hi
            wmma::mma_sync(acc[ip][0],     fal0, fbh[0], acc[ip][0]);
            wmma::mma_sync(acc[ip + 1][0], fal1, fbh[0], acc[ip + 1][0]);
            wmma::mma_sync(acc[ip][1],     fal0, fbh[1], acc[ip][1]);
            wmma::mma_sync(acc[ip + 1][1], fal1, fbh[1], acc[ip + 1][1]);
            // term hi*lo
            wmma::mma_sync(acc[ip][0],     fah0, fbl[0], acc[ip][0]);
            wmma::mma_sync(acc[ip + 1][0], fah1, fbl[0], acc[ip + 1][0]);
            wmma::mma_sync(acc[ip][1],     fah0, fbl[1], acc[ip][1]);
            wmma::mma_sync(acc[ip + 1][1], fah1, fbl[1], acc[ip + 1][1]);
        }
    }
    __syncthreads();   // before reusing dsm as epilogue bounce

    // epilogue: two 64-row phases through smem (64 x 132 f32)
    float* Cep = (float*)dsm;
    #pragma unroll
    for (int pm = 0; pm < 2; pm++) {
        if (wm == pm) {
            #pragma unroll
            for (int i = 0; i < 4; i++)
                #pragma unroll
                for (int j = 0; j < 2; j++)
                    wmma::store_matrix_sync(Cep + (i * 16) * 132 + wn * 32 + j * 16,
                                            acc[i][j], 132, wmma::mem_row_major);
        }
        __syncthreads();
        #pragma unroll
        for (int l = 0; l < 32; l++) {
            int e   = tid + 256 * l;
            int row = e >> 7;
            int col = e & 127;
            int gm  = m0 + pm * 64 + row;
            if (gm < M) {
                int gn = n0 + col;
                float vv = Cep[row * 132 + col] + bias[gn];
                if (mode == 1) {
                    vv = gelu_tanh(vv);
                    bf16 h, lo; split2(vv, h, lo);
                    Ch[(long)gm * N + gn] = h;
                    Cl[(long)gm * N + gn] = lo;
                } else {
                    if (res) vv += res[(long)gm * N + gn];
                    C[(long)gm * N + gn] = vv;
                }
            }
        }
        __syncthreads();
    }
}

// ---------------- fp32 SGEMM (head only: M=32, N=1000) ----------------
__global__ __launch_bounds__(256, 2)
void sgemm128(const float* __restrict__ A, const float* __restrict__ B,
              const float* __restrict__ bias, float* __restrict__ C,
              int M, int N, int K)
{
    __shared__ float As[16][128];
    __shared__ float Bs[16][128];

    const int tid = threadIdx.x;
    const int tx  = tid & 15;
    const int ty  = tid >> 4;
    const int m0  = blockIdx.y * 128;
    const int n0  = blockIdx.x * 128;

    float acc[8][8];
    #pragma unroll
    for (int i = 0; i < 8; i++)
        #pragma unroll
        for (int j = 0; j < 8; j++) acc[i][j] = 0.f;

    for (int k0 = 0; k0 < K; k0 += 16) {
        #pragma unroll
        for (int l = 0; l < 2; l++) {
            int e   = tid + 256 * l;
            int row = e >> 2;
            int c4  = (e & 3) * 4;
            int gm  = m0 + row;
            float4 av = make_float4(0.f, 0.f, 0.f, 0.f);
            if (gm < M) av = *(const float4*)(A + (long)gm * K + k0 + c4);
            As[c4 + 0][row] = av.x;
            As[c4 + 1][row] = av.y;
            As[c4 + 2][row] = av.z;
            As[c4 + 3][row] = av.w;
        }
        #pragma unroll
        for (int l = 0; l < 2; l++) {
            int e  = tid + 256 * l;
            int r  = e >> 5;
            int c  = (e & 31) * 4;
            int gn = n0 + c;
            const float* src = B + (long)(k0 + r) * N + gn;
            float4 bv;
            if (gn + 3 < N) {
                bv = *(const float4*)src;
            } else {
                bv.x = (gn + 0 < N) ? src[0] : 0.f;
                bv.y = (gn + 1 < N) ? src[1] : 0.f;
                bv.z = (gn + 2 < N) ? src[2] : 0.f;
                bv.w = (gn + 3 < N) ? src[3] : 0.f;
            }
            *(float4*)&Bs[r][c] = bv;
        }
        __syncthreads();

        #pragma unroll
        for (int kk = 0; kk < 16; kk++) {
            float ar[8], br[8];
            *(float4*)&ar[0] = *(const float4*)&As[kk][ty * 4];
            *(float4*)&ar[4] = *(const float4*)&As[kk][64 + ty * 4];
            *(float4*)&br[0] = *(const float4*)&Bs[kk][tx * 4];
            *(float4*)&br[4] = *(const float4*)&Bs[kk][64 + tx * 4];
            #pragma unroll
            for (int i = 0; i < 8; i++)
                #pragma unroll
                for (int j = 0; j < 8; j++)
                    acc[i][j] += ar[i] * br[j];
        }
        __syncthreads();
    }

    #pragma unroll
    for (int i = 0; i < 8; i++) {
        int gm = m0 + ((i < 4) ? (ty * 4 + i) : (64 + ty * 4 + i - 4));
        if (gm >= M) continue;
        #pragma unroll
        for (int j = 0; j < 8; j++) {
            int gn = n0 + ((j < 4) ? (tx * 4 + j) : (64 + tx * 4 + j - 4));
            if (gn >= N) continue;
            C[(long)gm * N + gn] = acc[i][j] + bias[gn];
        }
    }
}

// ---------------- LayerNorm -> bf16 hi/lo split output ----------------
__global__ void ln_split_kernel(const float* __restrict__ x, const float* __restrict__ g,
                                const float* __restrict__ b,
                                bf16* __restrict__ oh, bf16* __restrict__ ol)
{
    const int row = blockIdx.x;
    const int t   = threadIdx.x;   // 256
    const float* xr = x + (long)row * DIM;

    float v[3];
    float s = 0.f, s2 = 0.f;
    #pragma unroll
    for (int i = 0; i < 3; i++) {
        v[i] = xr[t + 256 * i];
        s  += v[i];
        s2 += v[i] * v[i];
    }
    #pragma unroll
    for (int off = 16; off; off >>= 1) {
        s  += __shfl_down_sync(0xffffffffu, s,  off);
        s2 += __shfl_down_sync(0xffffffffu, s2, off);
    }
    __shared__ float rs[8], rs2[8];
    int wid = t >> 5, lane = t & 31;
    if (lane == 0) { rs[wid] = s; rs2[wid] = s2; }
    __syncthreads();
    if (t == 0) {
        float a = 0.f, c = 0.f;
        #pragma unroll
        for (int i = 0; i < 8; i++) { a += rs[i]; c += rs2[i]; }
        rs[0] = a; rs2[0] = c;
    }
    __syncthreads();
    float mean = rs[0] * (1.f / DIM);
    float var  = rs2[0] * (1.f / DIM) - mean * mean;
    float rstd = rsqrtf(var + 1e-5f);
    #pragma unroll
    for (int i = 0; i < 3; i++) {
        int idx = t + 256 * i;
        float vv = (v[i] - mean) * rstd * g[idx] + b[idx];
        bf16 h, lo; split2(vv, h, lo);
        oh[(long)row * DIM + idx] = h;
        ol[(long)row * DIM + idx] = lo;
    }
}

// ---------------- LayerNorm fp32 out (head) ----------------
__global__ void ln_kernel(const float* __restrict__ x, const float* __restrict__ g,
                          const float* __restrict__ b, float* __restrict__ out)
{
    const int row = blockIdx.x;
    const int t   = threadIdx.x;
    const float* xr = x + (long)row * DIM;

    float v[3];
    float s = 0.f, s2 = 0.f;
    #pragma unroll
    for (int i = 0; i < 3; i++) {
        v[i] = xr[t + 256 * i];
        s  += v[i];
        s2 += v[i] * v[i];
    }
    #pragma unroll
    for (int off = 16; off; off >>= 1) {
        s  += __shfl_down_sync(0xffffffffu, s,  off);
        s2 += __shfl_down_sync(0xffffffffu, s2, off);
    }
    __shared__ float rs[8], rs2[8];
    int wid = t >> 5, lane = t & 31;
    if (lane == 0) { rs[wid] = s; rs2[wid] = s2; }
    __syncthreads();
    if (t == 0) {
        float a = 0.f, c = 0.f;
        #pragma unroll
        for (int i = 0; i < 8; i++) { a += rs[i]; c += rs2[i]; }
        rs[0] = a; rs2[0] = c;
    }
    __syncthreads();
    float mean = rs[0] * (1.f / DIM);
    float var  = rs2[0] * (1.f / DIM) - mean * mean;
    float rstd = rsqrtf(var + 1e-5f);
    float* orow = out + (long)row * DIM;
    #pragma unroll
    for (int i = 0; i < 3; i++) {
        int idx = t + 256 * i;
        orow[idx] = (v[i] - mean) * rstd * g[idx] + b[idx];
    }
}

// ---------------- generic fp32 -> bf16 hi/lo split ----------------
__global__ void split_kernel(const float* __restrict__ s, bf16* __restrict__ h,
                             bf16* __restrict__ l, int n)
{
    for (int i = blockIdx.x * blockDim.x + threadIdx.x; i < n; i += gridDim.x * blockDim.x) {
        bf16 hh, ll; split2(s[i], hh, ll);
        h[i] = hh; l[i] = ll;
    }
}

// ---------------- patch embedding support ----------------
__global__ void im2col_split_kernel(const float* __restrict__ imgs,
                                    bf16* __restrict__ ph, bf16* __restrict__ pl)
{
    long total = (long)PTOK * DIM;
    for (long idx = (long)blockIdx.x * blockDim.x + threadIdx.x; idx < total;
         idx += (long)gridDim.x * blockDim.x) {
        int row = (int)(idx / DIM);
        int col = (int)(idx % DIM);
        int b = row / 196, p = row % 196;
        int phh = p / 14, pw = p % 14;
        int c = col >> 8, rem = col & 255;
        int i = rem >> 4, j = rem & 15;
        float v = imgs[(((long)(b * 3 + c) * 224) + phh * 16 + i) * 224 + pw * 16 + j];
        bf16 h, lo; split2(v, h, lo);
        ph[idx] = h; pl[idx] = lo;
    }
}

// transpose 768x768 (OI -> IO) + split (patch weight [N][K] -> [K][N] bf16)
__global__ void transpose768_split_kernel(const float* __restrict__ w,
                                          bf16* __restrict__ wh, bf16* __restrict__ wl)
{
    int idx = blockIdx.x * 256 + threadIdx.x;
    if (idx < DIM * DIM) {
        int d = idx / DIM, k = idx % DIM;
        bf16 h, lo; split2(w[idx], h, lo);
        wh[k * DIM + d] = h; wl[k * DIM + d] = lo;
    }
}

// pack per-layer qkv weights (split, [K][N] layout) — weights already [K][N]
__global__ void qkv_pack_split_kernel(const float* __restrict__ wq, const float* __restrict__ wk,
                                      const float* __restrict__ wv,
                                      bf16* __restrict__ wh, bf16* __restrict__ wl)
{
    int total = DIM * QKVD;
    for (int idx = blockIdx.x * blockDim.x + threadIdx.x; idx < total;
         idx += gridDim.x * blockDim.x) {
        int k = idx / QKVD, n = idx % QKVD;
        int sel = n / DIM, c = n % DIM;
        const float* src = (sel == 0) ? wq : (sel == 1) ? wk : wv;
        bf16 h, lo; split2(src[k * DIM + c], h, lo);
        wh[idx] = h; wl[idx] = lo;
    }
}

// qkv bias concat
__global__ void bias3_kernel(const float* __restrict__ bq, const float* __restrict__ bk,
                             const float* __restrict__ bv, float* __restrict__ b)
{
    int i = blockIdx.x * 256 + threadIdx.x;
    if (i < QKVD) {
        int sel = i / DIM, c = i % DIM;
        b[i] = (sel == 0 ? bq : (sel == 1 ? bk : bv))[c];
    }
}

// assemble tokens
__global__ void assemble_kernel(const float* __restrict__ pe, const float* __restrict__ cls,
                                const float* __restrict__ pos, float* __restrict__ x)
{
    long total = (long)TOK * DIM;
    for (long idx = (long)blockIdx.x * blockDim.x + threadIdx.x; idx < total;
         idx += (long)gridDim.x * blockDim.x) {
        int row = (int)(idx / DIM);
        int d   = (int)(idx % DIM);
        int b = row / NTOK, n = row % NTOK;
        float v = (n == 0) ? cls[d] : pe[((long)(b * 196 + n - 1)) * DIM + d];
        x[idx] = v + pos[n * DIM + d];
    }
}

// ---------------- attention (q/k/v inside fused qkv buffer, row stride QKVD) ----
__global__ void attn_scores_kernel(const float* __restrict__ qkv, float* __restrict__ s)
{
    __shared__ float Qs[16][65], Ks[16][65];
    int bh = blockIdx.z;
    int b = bh / HEADS, hh = bh % HEADS;
    int tx = threadIdx.x, ty = threadIdx.y;
    int tid = ty * 16 + tx;
    int nbase = blockIdx.y * 16, mbase = blockIdx.x * 16;

    #pragma unroll
    for (int l = 0; l < 4; l++) {
        int e = tid + l * 256;
        int r = e >> 6, d = e & 63;
        int nq = nbase + r;
        Qs[r][d] = (nq < NTOK) ? qkv[((long)(b * NTOK + nq)) * QKVD + hh * DH + d] : 0.f;
        int mk = mbase + r;
        Ks[r][d] = (mk < NTOK) ? qkv[((long)(b * NTOK + mk)) * QKVD + DIM + hh * DH + d] : 0.f;
    }
    __syncthreads();

    float acc = 0.f;
    #pragma unroll
    for (int d = 0; d < DH; d++) acc += Qs[ty][d] * Ks[tx][d];

    int n = nbase + ty, m = mbase + tx;
    if (n < NTOK && m < NTOK)
        s[((long)bh * NTOK + n) * NTOK + m] = acc * 0.125f;
}

__global__ void softmax_kernel(float* __restrict__ s, int rows)
{
    int warp = (blockIdx.x * blockDim.x + threadIdx.x) >> 5;
    int lane = threadIdx.x & 31;
    if (warp >= rows) return;
    float* r = s + (long)warp * NTOK;

    float vals[7];
    float mx = -1e30f;
    #pragma unroll
    for (int w = 0; w < 7; w++) {
        int j = lane + 32 * w;
        vals[w] = (j < NTOK) ? r[j] : -1e30f;
        mx = fmaxf(mx, vals[w]);
    }
    #pragma unroll
    for (int off = 16; off; off >>= 1)
        mx = fmaxf(mx, __shfl_xor_sync(0xffffffffu, mx, off));

    float sum = 0.f;
    #pragma unroll
    for (int w = 0; w < 7; w++) {
        int j = lane + 32 * w;
        if (j < NTOK) { vals[w] = expf(vals[w] - mx); sum += vals[w]; }
    }
    #pragma unroll
    for (int off = 16; off; off >>= 1)
        sum += __shfl_xor_sync(0xffffffffu, sum, off);

    float inv = 1.f / sum;
    #pragma unroll
    for (int w = 0; w < 7; w++) {
        int j = lane + 32 * w;
        if (j < NTOK) r[j] = vals[w] * inv;
    }
}

// o = P @ V, written as bf16 hi/lo split
__global__ void attn_av_kernel(const float* __restrict__ s, const float* __restrict__ qkv,
                               bf16* __restrict__ oh, bf16* __restrict__ ol)
{
    __shared__ float Ps[16][17], Vs[16][17];
    int bh = blockIdx.z;
    int b = bh / HEADS, hh = bh % HEADS;
    int tx = threadIdx.x, ty = threadIdx.y;
    int n = blockIdx.y * 16 + ty;
    int d = blockIdx.x * 16 + tx;

    float acc = 0.f;
    for (int mt = 0; mt < 13; mt++) {
        int mP = mt * 16 + tx;
        Ps[ty][tx] = (n < NTOK && mP < NTOK) ? s[((long)bh * NTOK + n) * NTOK + mP] : 0.f;
        int mV = mt * 16 + ty;
        Vs[ty][tx] = (mV < NTOK)
            ? qkv[((long)(b * NTOK + mV)) * QKVD + 2 * DIM + hh * DH + d] : 0.f;
        __syncthreads();
        #pragma unroll
        for (int kk = 0; kk < 16; kk++) acc += Ps[ty][kk] * Vs[kk][tx];
        __syncthreads();
    }
    if (n < NTOK) {
        bf16 h, lo; split2(acc, h, lo);
        long idx = ((long)(b * NTOK + n)) * DIM + hh * DH + d;
        oh[idx] = h; ol[idx] = lo;
    }
}

// ---------------- mean pool ----------------
__global__ void pool_kernel(const float* __restrict__ x, float* __restrict__ out)
{
    int b = blockIdx.x;
    for (int d = threadIdx.x; d < DIM; d += blockDim.x) {
        float s = 0.f;
        for (int n = 0; n < NTOK; n++)
            s += x[((long)(b * NTOK + n)) * DIM + d];
        out[b * DIM + d] = s * (1.f / NTOK);
    }
}

// ---------------- host ----------------
extern "C" void kernel_launch(void* const* d_in, const int* in_sizes, int n_in,
                              void* d_out, int out_size)
{
    const float* imgs    = (const float*)d_in[0];
    const float* patch_w = (const float*)d_in[1];
    const float* patch_b = (const float*)d_in[2];
    const float* cls     = (const float*)d_in[3];
    const float* pos     = (const float*)d_in[4];
    const float* ln1_g   = (const float*)d_in[5];
    const float* ln1_b   = (const float*)d_in[6];
    const float* wq      = (const float*)d_in[7];
    const float* bq      = (const float*)d_in[8];
    const float* wk      = (const float*)d_in[9];
    const float* bk      = (const float*)d_in[10];
    const float* wv      = (const float*)d_in[11];
    const float* bv      = (const float*)d_in[12];
    const float* wo      = (const float*)d_in[13];
    const float* bo      = (const float*)d_in[14];
    const float* ln2_g   = (const float*)d_in[15];
    const float* ln2_b   = (const float*)d_in[16];
    const float* w1      = (const float*)d_in[17];
    const float* b1      = (const float*)d_in[18];
    const float* w2      = (const float*)d_in[19];
    const float* b2      = (const float*)d_in[20];
    const float* hn_g    = (const float*)d_in[21];
    const float* hn_b    = (const float*)d_in[22];
    const float* hw      = (const float*)d_in[23];
    const float* hb      = (const float*)d_in[24];
    float* out = (float*)d_out;

    float *att, *x, *qkv, *bqkv, *pool, *pooln;
    bf16 *hh, *hl, *oh, *ol, *mh, *ml, *ph, *pl, *wth, *wtl, *wqh, *wql;
    bf16 *woh, *wol, *w1h, *w1l, *w2h, *w2l;
    cudaGetSymbolAddress((void**)&att,   g_att);
    cudaGetSymbolAddress((void**)&x,     g_x);
    cudaGetSymbolAddress((void**)&qkv,   g_qkv);
    cudaGetSymbolAddress((void**)&bqkv,  g_bqkv);
    cudaGetSymbolAddress((void**)&pool,  g_pool);
    cudaGetSymbolAddress((void**)&pooln, g_pooln);
    cudaGetSymbolAddress((void**)&hh,  g_hh);  cudaGetSymbolAddress((void**)&hl,  g_hl);
    cudaGetSymbolAddress((void**)&oh,  g_oh);  cudaGetSymbolAddress((void**)&ol,  g_ol);
    cudaGetSymbolAddress((void**)&mh,  g_mh);  cudaGetSymbolAddress((void**)&ml,  g_ml);
    cudaGetSymbolAddress((void**)&ph,  g_ph);  cudaGetSymbolAddress((void**)&pl,  g_pl);
    cudaGetSymbolAddress((void**)&wth, g_wth); cudaGetSymbolAddress((void**)&wtl, g_wtl);
    cudaGetSymbolAddress((void**)&wqh, g_wqh); cudaGetSymbolAddress((void**)&wql, g_wql);
    cudaGetSymbolAddress((void**)&woh, g_woh); cudaGetSymbolAddress((void**)&wol, g_wol);
    cudaGetSymbolAddress((void**)&w1h, g_w1h); cudaGetSymbolAddress((void**)&w1l, g_w1l);
    cudaGetSymbolAddress((void**)&w2h, g_w2h); cudaGetSymbolAddress((void**)&w2l, g_w2l);

    cudaFuncSetAttribute(gemm_bf16s, cudaFuncAttributeMaxDynamicSharedMemorySize, GEMM_DSMEM);

    auto gemmS = [](const bf16* Ah, const bf16* Al, const bf16* Bh, const bf16* Bl,
                    const float* bias, const float* res, float* C, bf16* Ch, bf16* Cl,
                    int M, int N, int K, int mode) {
        dim3 grid(N / 128, (M + 127) / 128);
        gemm_bf16s<<<grid, 256, GEMM_DSMEM>>>(Ah, Al, Bh, Bl, bias, res, C, Ch, Cl, M, N, K, mode);
    };

    // ---- patch embedding (bias3 for layer 0 inserted as 3rd launch so the
    //      profiler's fixed capture slot (4th launch) lands on gemm_bf16s) ----
    im2col_split_kernel<<<4096, 256>>>(imgs, ph, pl);                              // 1
    transpose768_split_kernel<<<(DIM * DIM + 255) / 256, 256>>>(patch_w, wth, wtl); // 2
    bias3_kernel<<<9, 256>>>(bq, bk, bv, bqkv);                                    // 3 (layer 0)
    gemmS(ph, pl, wth, wtl, patch_b, nullptr, qkv, nullptr, nullptr, PTOK, DIM, DIM, 0); // 4
    assemble_kernel<<<4096, 256>>>(qkv, cls, pos, x);

    // ---- transformer layers ----
    const int rows_sm = BATCH * HEADS * NTOK;
    for (int i = 0; i < LAYERS; i++) {
        qkv_pack_split_kernel<<<2048, 256>>>(wq + (long)i * DIM * DIM, wk + (long)i * DIM * DIM,
                                             wv + (long)i * DIM * DIM, wqh, wql);
        if (i > 0) bias3_kernel<<<9, 256>>>(bq + i * DIM, bk + i * DIM, bv + i * DIM, bqkv);
        split_kernel<<<1024, 256>>>(wo + (long)i * DIM * DIM, woh, wol, DIM * DIM);
        split_kernel<<<2048, 256>>>(w1 + (long)i * DIM * MLPD, w1h, w1l, DIM * MLPD);
        split_kernel<<<2048, 256>>>(w2 + (long)i * MLPD * DIM, w2h, w2l, MLPD * DIM);

        ln_split_kernel<<<TOK, 256>>>(x, ln1_g + i * DIM, ln1_b + i * DIM, hh, hl);
        gemmS(hh, hl, wqh, wql, bqkv, nullptr, qkv, nullptr, nullptr, TOK, QKVD, DIM, 0);

        attn_scores_kernel<<<dim3(13, 13, BATCH * HEADS), dim3(16, 16)>>>(qkv, att);
        softmax_kernel<<<(rows_sm * 32 + 255) / 256, 256>>>(att, rows_sm);
        attn_av_kernel<<<dim3(4, 13, BATCH * HEADS), dim3(16, 16)>>>(att, qkv, oh, ol);

        gemmS(oh, ol, woh, wol, bo + i * DIM, x, x, nullptr, nullptr, TOK, DIM, DIM, 0);

        ln_split_kernel<<<TOK, 256>>>(x, ln2_g + i * DIM, ln2_b + i * DIM, hh, hl);
        gemmS(hh, hl, w1h, w1l, b1 + i * MLPD, nullptr, nullptr, mh, ml, TOK, MLPD, DIM, 1);
        gemmS(mh, ml, w2h, w2l, b2 + i * DIM, x, x, nullptr, nullptr, TOK, DIM, MLPD, 0);
    }

    // ---- head ----
    pool_kernel<<<BATCH, 256>>>(x, pool);
    ln_kernel<<<BATCH, 256>>>(pool, hn_g, hn_b, pooln);
    {
        dim3 grid((NC + 127) / 128, 1);
        sgemm128<<<grid, 256>>>(pooln, hw, hb, out, BATCH, NC, DIM);
    }
}